// round 2
// baseline (speedup 1.0000x reference)
#include <cuda_runtime.h>
#include <math.h>

#define BB 1024
#define DD 512
#define HH 1024
#define TT 8
#define EE 18

// Scratch (no cudaMalloc allowed): ~133 MB total
__device__ float g_h  [BB * EE * HH];   // expert hidden, (B, E, H)
__device__ float g_eo [BB * EE * DD];   // expert out,    (B, E, D)
__device__ float g_gate[BB * 9 * EE];   // gates,         (B, M, E)
__device__ float g_x1 [BB * 9 * DD];    // layer-0 output (B, 9, D)

// ---------------------------------------------------------------------------
// Batched expert GEMM: C[b, e, n] = act( sum_k A_row(b,e)[k] * W[e,k,n] + bias[e,n] )
//   GATHER=true : A row for (b,e) = A + (b*aRowStride + (e>>1)*K)   (expert gather)
//   GATHER=false: A row for (b,e) = A + (b*aRowStride + e*K)
// Tiles: 128x128x8, 256 threads, 8x8 per-thread register tile.
// ---------------------------------------------------------------------------
template<bool GATHER, bool RELU, int N, int K>
__global__ __launch_bounds__(256) void expert_gemm(
    const float* __restrict__ A, int aRowStride,
    const float* __restrict__ W,
    const float* __restrict__ bias,
    float* __restrict__ C)
{
    __shared__ float As[8][128];
    __shared__ float Bs[8][128];

    const int e   = blockIdx.z;
    const int m0  = blockIdx.y * 128;
    const int n0  = blockIdx.x * 128;
    const int tid = threadIdx.x;

    const int aOff = (GATHER ? (e >> 1) : e) * K;
    const float* Wp = W + (size_t)e * K * N;

    // A tile load mapping: 128 rows x 8 k, one float4 per thread
    const int arow = tid >> 1;
    const int akq  = (tid & 1) * 4;
    const float* aPtr = A + (size_t)(m0 + arow) * aRowStride + aOff + akq;

    // W tile load mapping: 8 k-rows x 128 cols, one float4 per thread (coalesced)
    const int brow = tid >> 5;
    const int bcol = (tid & 31) * 4;
    const float* wPtr = Wp + (size_t)brow * N + n0 + bcol;

    const int trow = (tid >> 4) * 8;
    const int tcol = (tid & 15) * 8;

    float acc[8][8];
    #pragma unroll
    for (int i = 0; i < 8; i++)
        #pragma unroll
        for (int j = 0; j < 8; j++) acc[i][j] = 0.f;

    for (int kt = 0; kt < K; kt += 8) {
        float4 av = *(const float4*)(aPtr + kt);
        float4 wv = *(const float4*)(wPtr + (size_t)kt * N);
        As[akq + 0][arow] = av.x;
        As[akq + 1][arow] = av.y;
        As[akq + 2][arow] = av.z;
        As[akq + 3][arow] = av.w;
        *(float4*)&Bs[brow][bcol] = wv;
        __syncthreads();

        #pragma unroll
        for (int kk = 0; kk < 8; kk++) {
            float a[8], b[8];
            *(float4*)&a[0] = *(const float4*)&As[kk][trow];
            *(float4*)&a[4] = *(const float4*)&As[kk][trow + 4];
            *(float4*)&b[0] = *(const float4*)&Bs[kk][tcol];
            *(float4*)&b[4] = *(const float4*)&Bs[kk][tcol + 4];
            #pragma unroll
            for (int i = 0; i < 8; i++)
                #pragma unroll
                for (int j = 0; j < 8; j++)
                    acc[i][j] = fmaf(a[i], b[j], acc[i][j]);
        }
        __syncthreads();
    }

    float bb[8];
    #pragma unroll
    for (int j = 0; j < 8; j++) bb[j] = bias[(size_t)e * N + n0 + tcol + j];

    #pragma unroll
    for (int i = 0; i < 8; i++) {
        float* cp = C + ((size_t)(m0 + trow + i) * EE + e) * N + n0 + tcol;
        float v[8];
        #pragma unroll
        for (int j = 0; j < 8; j++) {
            v[j] = acc[i][j] + bb[j];
            if (RELU) v[j] = fmaxf(v[j], 0.f);
        }
        *(float4*)(cp)     = make_float4(v[0], v[1], v[2], v[3]);
        *(float4*)(cp + 4) = make_float4(v[4], v[5], v[6], v[7]);
    }
}

// ---------------------------------------------------------------------------
// Gating: g[b,m,:] = softmax( x[b,m,:] @ Wg[m] + bg[m] ) + add(m)
// grid: (B/32, M), block 256. Wg[m] (512x18) staged in smem.
// ---------------------------------------------------------------------------
template<int M>
__global__ __launch_bounds__(256) void gate_kernel(
    const float* __restrict__ x, int xRows,
    const float* __restrict__ Wg, const float* __restrict__ bg,
    const float* __restrict__ sew_task, const float* __restrict__ sew_shared,
    int layer, float* __restrict__ g)
{
    __shared__ float sWg[DD * EE];
    __shared__ float sLog[32][EE];
    const int m  = blockIdx.y;
    const int b0 = blockIdx.x * 32;

    const float* Wgm = Wg + (size_t)m * DD * EE;
    for (int i = threadIdx.x; i < DD * EE; i += 256) sWg[i] = Wgm[i];
    __syncthreads();

    for (int p = threadIdx.x; p < 32 * EE; p += 256) {
        const int bl = p / EE, e = p % EE;
        const float* xr = x + ((size_t)(b0 + bl) * xRows + m) * DD;
        float s = bg[m * EE + e];
        for (int d = 0; d < DD; d += 4) {
            float4 xv = *(const float4*)(xr + d);
            s = fmaf(xv.x, sWg[(d + 0) * EE + e], s);
            s = fmaf(xv.y, sWg[(d + 1) * EE + e], s);
            s = fmaf(xv.z, sWg[(d + 2) * EE + e], s);
            s = fmaf(xv.w, sWg[(d + 3) * EE + e], s);
        }
        sLog[bl][e] = s;
    }
    __syncthreads();

    if (threadIdx.x < 32) {
        const int bl = threadIdx.x;
        float mx = -1e30f;
        #pragma unroll
        for (int e = 0; e < EE; e++) mx = fmaxf(mx, sLog[bl][e]);
        float ex[EE]; float sum = 0.f;
        #pragma unroll
        for (int e = 0; e < EE; e++) { ex[e] = expf(sLog[bl][e] - mx); sum += ex[e]; }
        const float inv = 1.f / sum;
        float* gp = g + ((size_t)(b0 + bl) * M + m) * EE;
        #pragma unroll
        for (int e = 0; e < EE; e++) gp[e] = ex[e] * inv;
        if (m < TT) {
            gp[2 * m + 0] += sew_task[(m * 2 + layer) * 2 + 0];
            gp[2 * m + 1] += sew_task[(m * 2 + layer) * 2 + 1];
        } else {
            gp[16] += sew_shared[0];
            gp[17] += sew_shared[1];
        }
    }
}

// ---------------------------------------------------------------------------
// Combine: out[b,m,d] = sum_e g[b,m,e] * eo[b,e,d]. One block per b, 512 thr.
// ---------------------------------------------------------------------------
template<int M>
__global__ __launch_bounds__(512) void combine_kernel(
    const float* __restrict__ g, const float* __restrict__ eo,
    float* __restrict__ out)
{
    __shared__ float sg[M * EE];
    const int b = blockIdx.x;
    for (int i = threadIdx.x; i < M * EE; i += 512) sg[i] = g[(size_t)b * M * EE + i];
    __syncthreads();

    const int d = threadIdx.x;
    float acc[M];
    #pragma unroll
    for (int mm = 0; mm < M; mm++) acc[mm] = 0.f;

    const float* eob = eo + (size_t)b * EE * DD + d;
    #pragma unroll
    for (int e = 0; e < EE; e++) {
        const float v = eob[(size_t)e * DD];
        #pragma unroll
        for (int mm = 0; mm < M; mm++) acc[mm] = fmaf(sg[mm * EE + e], v, acc[mm]);
    }
    #pragma unroll
    for (int mm = 0; mm < M; mm++)
        out[((size_t)b * M + mm) * DD + d] = acc[mm];
}

// ---------------------------------------------------------------------------
extern "C" void kernel_launch(void* const* d_in, const int* in_sizes, int n_in,
                              void* d_out, int out_size)
{
    const float* inputs   = (const float*)d_in[0];
    const float* W1_0     = (const float*)d_in[1];
    const float* b1_0     = (const float*)d_in[2];
    const float* W2_0     = (const float*)d_in[3];
    const float* b2_0     = (const float*)d_in[4];
    const float* Wg_0     = (const float*)d_in[5];
    const float* bg_0     = (const float*)d_in[6];
    const float* W1_1     = (const float*)d_in[7];
    const float* b1_1     = (const float*)d_in[8];
    const float* W2_1     = (const float*)d_in[9];
    const float* b2_1     = (const float*)d_in[10];
    const float* Wg_1     = (const float*)d_in[11];
    const float* bg_1     = (const float*)d_in[12];
    const float* sew_task = (const float*)d_in[13];
    const float* sew_shared = (const float*)d_in[14];

    float *p_h, *p_eo, *p_gate, *p_x1;
    cudaGetSymbolAddress((void**)&p_h,    g_h);
    cudaGetSymbolAddress((void**)&p_eo,   g_eo);
    cudaGetSymbolAddress((void**)&p_gate, g_gate);
    cudaGetSymbolAddress((void**)&p_x1,   g_x1);

    const dim3 blk(256);

    // ---- Layer 0 ----
    expert_gemm<true,  true,  HH, DD><<<dim3(HH/128, BB/128, EE), blk>>>(inputs, 9 * DD, W1_0, b1_0, p_h);
    expert_gemm<false, false, DD, HH><<<dim3(DD/128, BB/128, EE), blk>>>(p_h, EE * HH, W2_0, b2_0, p_eo);
    gate_kernel<9><<<dim3(BB/32, 9), blk>>>(inputs, 9, Wg_0, bg_0, sew_task, sew_shared, 0, p_gate);
    combine_kernel<9><<<BB, 512>>>(p_gate, p_eo, p_x1);

    // ---- Layer 1 ----
    expert_gemm<true,  true,  HH, DD><<<dim3(HH/128, BB/128, EE), blk>>>(p_x1, 9 * DD, W1_1, b1_1, p_h);
    expert_gemm<false, false, DD, HH><<<dim3(DD/128, BB/128, EE), blk>>>(p_h, EE * HH, W2_1, b2_1, p_eo);
    gate_kernel<8><<<dim3(BB/32, 8), blk>>>(p_x1, 9, Wg_1, bg_1, sew_task, sew_shared, 1, p_gate);
    combine_kernel<8><<<BB, 512>>>(p_gate, p_eo, (float*)d_out);
}

// round 5
// speedup vs baseline: 1.3387x; 1.3387x over previous
#include <cuda_runtime.h>
#include <cuda_bf16.h>
#include <cstdint>
#include <math.h>

#define BB 1024
#define DD 512
#define HH 1024
#define TT 8
#define EE 18

// Scratch (no cudaMalloc allowed)
__device__ float g_h  [BB * EE * HH];   // expert hidden, (B, E, H)
__device__ float g_eo [BB * EE * DD];   // expert out,    (B, E, D)
__device__ float g_gate[BB * 9 * EE];   // gates,         (B, M, E)
__device__ float g_x1 [BB * 9 * DD];    // layer-0 output (B, 9, D)

// ---------------------------------------------------------------------------
// bf16 hi/lo split: x ~= hi + lo, error ~2^-18 relative
// ---------------------------------------------------------------------------
__device__ __forceinline__ void split2(float x, float y, uint32_t& hi, uint32_t& lo) {
    __nv_bfloat16 hx = __float2bfloat16_rn(x);
    __nv_bfloat16 hy = __float2bfloat16_rn(y);
    __nv_bfloat16 lx = __float2bfloat16_rn(x - __bfloat162float(hx));
    __nv_bfloat16 ly = __float2bfloat16_rn(y - __bfloat162float(hy));
    hi = (uint32_t)__bfloat16_as_ushort(hx) | ((uint32_t)__bfloat16_as_ushort(hy) << 16);
    lo = (uint32_t)__bfloat16_as_ushort(lx) | ((uint32_t)__bfloat16_as_ushort(ly) << 16);
}

__device__ __forceinline__ void mma16816(float* c, const uint32_t* a, const uint32_t* b) {
    asm volatile(
        "mma.sync.aligned.m16n8k16.row.col.f32.bf16.bf16.f32 "
        "{%0,%1,%2,%3}, {%4,%5,%6,%7}, {%8,%9}, {%0,%1,%2,%3};"
        : "+f"(c[0]), "+f"(c[1]), "+f"(c[2]), "+f"(c[3])
        : "r"(a[0]), "r"(a[1]), "r"(a[2]), "r"(a[3]), "r"(b[0]), "r"(b[1]));
}

// ===========================================================================
// Tensor-core expert GEMM via mma.sync bf16 3-product split (fp32 accuracy):
//   C[b, e, n] = act( sum_k A_row(b,e)[k] * W[e,k,n] + bias[e,n] )
// Tile 128x128, BK=32 slabs, double-buffered SMEM (reg-staged converts).
// 256 threads = 8 warps in 2x4 grid; warp tile 64x32; m16n8k16 fragments
// loaded as single LDS.32 each (K-major bf16 rows padded to 80B => conflict-free).
// SMEM stage (words): [Ahi 2560][Alo 2560][Bhi 2560][Blo 2560] = 40KB, x2 stages.
// ===========================================================================
template<bool GATHER, bool RELU, int NMAT, int K>
__global__ __launch_bounds__(256, 1) void tc_gemm(
    const float* __restrict__ A, int aRowStride,
    const float* __restrict__ W,
    const float* __restrict__ bias,
    float* __restrict__ C)
{
    constexpr int NS   = K / 32;       // K slabs
    constexpr int ROWW = 20;           // words per smem row (32 bf16 = 16w + 4 pad)
    constexpr int SEC  = 128 * ROWW;   // words per matrix section (2560)
    constexpr int STG  = 4 * SEC;      // words per stage (10240)

    extern __shared__ uint32_t smw[];

    const int e    = blockIdx.z;
    const int m0   = blockIdx.y * 128;
    const int n0   = blockIdx.x * 128;
    const int tid  = threadIdx.x;
    const int wid  = tid >> 5;
    const int lane = tid & 31;
    const int g    = lane >> 2;        // quad group 0..7
    const int q    = lane & 3;         // quad lane  0..3
    const int mbase = (wid >> 2) * 64; // warp row tile
    const int nbase = (wid & 3) * 32;  // warp col tile

    const float* Ab = A + (size_t)m0 * aRowStride + (size_t)(GATHER ? (e >> 1) : e) * K;
    const float* Wb = W + (size_t)e * K * NMAT + n0;

    // ---- global staging (converted to bf16 hi/lo words) ----
    uint32_t sAh[8], sAl[8], sBh[8], sBl[8];
    const int arow = tid >> 1;          // 0..127
    const int akh  = (tid & 1) * 16;    // k half within slab
    const int bn0  = (lane) * 4;        // 4 n per thread (lane 0..31 -> n 0..124)
    const int bkg  = wid;               // k group 0..7 (x4 k)

    float acc[4][4][4];
    #pragma unroll
    for (int i = 0; i < 4; i++)
        #pragma unroll
        for (int j = 0; j < 4; j++)
            #pragma unroll
            for (int c = 0; c < 4; c++) acc[i][j][c] = 0.f;

    auto loadSlab = [&](int s) {
        const float* ap = Ab + (size_t)arow * aRowStride + s * 32 + akh;
        #pragma unroll
        for (int w = 0; w < 4; w++) {
            float4 v = *(const float4*)(ap + w * 4);
            split2(v.x, v.y, sAh[2 * w],     sAl[2 * w]);
            split2(v.z, v.w, sAh[2 * w + 1], sAl[2 * w + 1]);
        }
        const float* bp = Wb + (size_t)(s * 32 + bkg * 4) * NMAT + bn0;
        float bk[4][4];
        *(float4*)bk[0] = *(const float4*)(bp);
        *(float4*)bk[1] = *(const float4*)(bp + NMAT);
        *(float4*)bk[2] = *(const float4*)(bp + 2 * NMAT);
        *(float4*)bk[3] = *(const float4*)(bp + 3 * NMAT);
        #pragma unroll
        for (int j = 0; j < 4; j++) {
            split2(bk[0][j], bk[1][j], sBh[2 * j],     sBl[2 * j]);
            split2(bk[2][j], bk[3][j], sBh[2 * j + 1], sBl[2 * j + 1]);
        }
    };

    auto storeSlab = [&](int buf) {
        uint32_t* st = smw + buf * STG;
        const int aoff = arow * ROWW + (tid & 1) * 8;
        #pragma unroll
        for (int w = 0; w < 4; w++) {
            *(uint2*)&st[aoff + 2 * w]       = make_uint2(sAh[2 * w], sAh[2 * w + 1]);
            *(uint2*)&st[SEC + aoff + 2 * w] = make_uint2(sAl[2 * w], sAl[2 * w + 1]);
        }
        #pragma unroll
        for (int j = 0; j < 4; j++) {
            const int boff = (bn0 + j) * ROWW + bkg * 2;
            *(uint2*)&st[2 * SEC + boff] = make_uint2(sBh[2 * j], sBh[2 * j + 1]);
            *(uint2*)&st[3 * SEC + boff] = make_uint2(sBl[2 * j], sBl[2 * j + 1]);
        }
    };

    auto compute = [&](int buf) {
        const uint32_t* Ah = smw + buf * STG;
        const uint32_t* Al = Ah + SEC;
        const uint32_t* Bh = Ah + 2 * SEC;
        const uint32_t* Bl = Ah + 3 * SEC;
        #pragma unroll
        for (int ks = 0; ks < 2; ks++) {
            const int w0 = ks * 8 + q;
            uint32_t ah[4][4], al[4][4], bh[4][2], bl[4][2];
            #pragma unroll
            for (int i = 0; i < 4; i++) {
                const int r = (mbase + i * 16 + g) * ROWW;
                ah[i][0] = Ah[r + w0];
                ah[i][1] = Ah[r + 8 * ROWW + w0];
                ah[i][2] = Ah[r + w0 + 4];
                ah[i][3] = Ah[r + 8 * ROWW + w0 + 4];
                al[i][0] = Al[r + w0];
                al[i][1] = Al[r + 8 * ROWW + w0];
                al[i][2] = Al[r + w0 + 4];
                al[i][3] = Al[r + 8 * ROWW + w0 + 4];
            }
            #pragma unroll
            for (int j = 0; j < 4; j++) {
                const int n = (nbase + j * 8 + g) * ROWW;
                bh[j][0] = Bh[n + w0];
                bh[j][1] = Bh[n + w0 + 4];
                bl[j][0] = Bl[n + w0];
                bl[j][1] = Bl[n + w0 + 4];
            }
            #pragma unroll
            for (int i = 0; i < 4; i++)
                #pragma unroll
                for (int j = 0; j < 4; j++) {
                    mma16816(acc[i][j], ah[i], bh[j]);
                    mma16816(acc[i][j], ah[i], bl[j]);
                    mma16816(acc[i][j], al[i], bh[j]);
                }
        }
    };

    // ---- main loop: reg-staged double buffer, 1 barrier per slab ----
    loadSlab(0);
    storeSlab(0);
    __syncthreads();
    for (int s = 0; s < NS; s++) {
        if (s + 1 < NS) loadSlab(s + 1);
        compute(s & 1);
        if (s + 1 < NS) {
            storeSlab((s + 1) & 1);
            __syncthreads();
        }
    }

    // ---- epilogue: bias + optional relu, fp32 stores ----
    #pragma unroll
    for (int i = 0; i < 4; i++) {
        const int r0 = m0 + mbase + i * 16 + g;
        float* cp0 = C + ((size_t)r0 * EE + e) * NMAT + n0;
        float* cp1 = cp0 + (size_t)8 * EE * NMAT;
        #pragma unroll
        for (int j = 0; j < 4; j++) {
            const int col = nbase + j * 8 + 2 * q;
            const float2 bb = *(const float2*)(bias + (size_t)e * NMAT + n0 + col);
            float v0 = acc[i][j][0] + bb.x;
            float v1 = acc[i][j][1] + bb.y;
            float v2 = acc[i][j][2] + bb.x;
            float v3 = acc[i][j][3] + bb.y;
            if (RELU) {
                v0 = fmaxf(v0, 0.f); v1 = fmaxf(v1, 0.f);
                v2 = fmaxf(v2, 0.f); v3 = fmaxf(v3, 0.f);
            }
            *(float2*)(cp0 + col) = make_float2(v0, v1);
            *(float2*)(cp1 + col) = make_float2(v2, v3);
        }
    }
}

// ---------------------------------------------------------------------------
// Gating: g[b,m,:] = softmax( x[b,m,:] @ Wg[m] + bg[m] ) + add(m)
// ---------------------------------------------------------------------------
template<int M>
__global__ __launch_bounds__(256) void gate_kernel(
    const float* __restrict__ x, int xRows,
    const float* __restrict__ Wg, const float* __restrict__ bg,
    const float* __restrict__ sew_task, const float* __restrict__ sew_shared,
    int layer, float* __restrict__ g)
{
    __shared__ float sWg[DD * EE];
    __shared__ float sLog[32][EE];
    const int m  = blockIdx.y;
    const int b0 = blockIdx.x * 32;

    const float* Wgm = Wg + (size_t)m * DD * EE;
    for (int i = threadIdx.x; i < DD * EE; i += 256) sWg[i] = Wgm[i];
    __syncthreads();

    for (int p = threadIdx.x; p < 32 * EE; p += 256) {
        const int bl = p / EE, e = p % EE;
        const float* xr = x + ((size_t)(b0 + bl) * xRows + m) * DD;
        float s = bg[m * EE + e];
        for (int d = 0; d < DD; d += 4) {
            float4 xv = *(const float4*)(xr + d);
            s = fmaf(xv.x, sWg[(d + 0) * EE + e], s);
            s = fmaf(xv.y, sWg[(d + 1) * EE + e], s);
            s = fmaf(xv.z, sWg[(d + 2) * EE + e], s);
            s = fmaf(xv.w, sWg[(d + 3) * EE + e], s);
        }
        sLog[bl][e] = s;
    }
    __syncthreads();

    if (threadIdx.x < 32) {
        const int bl = threadIdx.x;
        float mx = -1e30f;
        #pragma unroll
        for (int e = 0; e < EE; e++) mx = fmaxf(mx, sLog[bl][e]);
        float ex[EE]; float sum = 0.f;
        #pragma unroll
        for (int e = 0; e < EE; e++) { ex[e] = expf(sLog[bl][e] - mx); sum += ex[e]; }
        const float inv = 1.f / sum;
        float* gp = g + ((size_t)(b0 + bl) * M + m) * EE;
        #pragma unroll
        for (int e = 0; e < EE; e++) gp[e] = ex[e] * inv;
        if (m < TT) {
            gp[2 * m + 0] += sew_task[(m * 2 + layer) * 2 + 0];
            gp[2 * m + 1] += sew_task[(m * 2 + layer) * 2 + 1];
        } else {
            gp[16] += sew_shared[0];
            gp[17] += sew_shared[1];
        }
    }
}

// ---------------------------------------------------------------------------
// Combine: out[b,m,d] = sum_e g[b,m,e] * eo[b,e,d]
// ---------------------------------------------------------------------------
template<int M>
__global__ __launch_bounds__(512) void combine_kernel(
    const float* __restrict__ g, const float* __restrict__ eo,
    float* __restrict__ out)
{
    __shared__ float sg[M * EE];
    const int b = blockIdx.x;
    for (int i = threadIdx.x; i < M * EE; i += 512) sg[i] = g[(size_t)b * M * EE + i];
    __syncthreads();

    const int d = threadIdx.x;
    float acc[M];
    #pragma unroll
    for (int mm = 0; mm < M; mm++) acc[mm] = 0.f;

    const float* eob = eo + (size_t)b * EE * DD + d;
    #pragma unroll
    for (int e = 0; e < EE; e++) {
        const float v = eob[(size_t)e * DD];
        #pragma unroll
        for (int mm = 0; mm < M; mm++) acc[mm] = fmaf(sg[mm * EE + e], v, acc[mm]);
    }
    #pragma unroll
    for (int mm = 0; mm < M; mm++)
        out[((size_t)b * M + mm) * DD + d] = acc[mm];
}

// ---------------------------------------------------------------------------
extern "C" void kernel_launch(void* const* d_in, const int* in_sizes, int n_in,
                              void* d_out, int out_size)
{
    const float* inputs   = (const float*)d_in[0];
    const float* W1_0     = (const float*)d_in[1];
    const float* b1_0     = (const float*)d_in[2];
    const float* W2_0     = (const float*)d_in[3];
    const float* b2_0     = (const float*)d_in[4];
    const float* Wg_0     = (const float*)d_in[5];
    const float* bg_0     = (const float*)d_in[6];
    const float* W1_1     = (const float*)d_in[7];
    const float* b1_1     = (const float*)d_in[8];
    const float* W2_1     = (const float*)d_in[9];
    const float* b2_1     = (const float*)d_in[10];
    const float* Wg_1     = (const float*)d_in[11];
    const float* bg_1     = (const float*)d_in[12];
    const float* sew_task = (const float*)d_in[13];
    const float* sew_shared = (const float*)d_in[14];

    float *p_h, *p_eo, *p_gate, *p_x1;
    cudaGetSymbolAddress((void**)&p_h,    g_h);
    cudaGetSymbolAddress((void**)&p_eo,   g_eo);
    cudaGetSymbolAddress((void**)&p_gate, g_gate);
    cudaGetSymbolAddress((void**)&p_x1,   g_x1);

    const int SMEM_DYN = 2 * 40960;   // 80 KB
    cudaFuncSetAttribute(tc_gemm<true,  true,  HH, DD>,
                         cudaFuncAttributeMaxDynamicSharedMemorySize, SMEM_DYN);
    cudaFuncSetAttribute(tc_gemm<false, false, DD, HH>,
                         cudaFuncAttributeMaxDynamicSharedMemorySize, SMEM_DYN);

    const dim3 blk(256);

    // ---- Layer 0 ----
    tc_gemm<true,  true,  HH, DD><<<dim3(HH/128, BB/128, EE), blk, SMEM_DYN>>>(inputs, 9 * DD, W1_0, b1_0, p_h);
    tc_gemm<false, false, DD, HH><<<dim3(DD/128, BB/128, EE), blk, SMEM_DYN>>>(p_h, EE * HH, W2_0, b2_0, p_eo);
    gate_kernel<9><<<dim3(BB/32, 9), blk>>>(inputs, 9, Wg_0, bg_0, sew_task, sew_shared, 0, p_gate);
    combine_kernel<9><<<BB, 512>>>(p_gate, p_eo, p_x1);

    // ---- Layer 1 ----
    tc_gemm<true,  true,  HH, DD><<<dim3(HH/128, BB/128, EE), blk, SMEM_DYN>>>(p_x1, 9 * DD, W1_1, b1_1, p_h);
    tc_gemm<false, false, DD, HH><<<dim3(DD/128, BB/128, EE), blk, SMEM_DYN>>>(p_h, EE * HH, W2_1, b2_1, p_eo);
    gate_kernel<8><<<dim3(BB/32, 8), blk>>>(p_x1, 9, Wg_1, bg_1, sew_task, sew_shared, 1, p_gate);
    combine_kernel<8><<<BB, 512>>>(p_gate, p_eo, (float*)d_out);
}

// round 6
// speedup vs baseline: 2.2493x; 1.6802x over previous
#include <cuda_runtime.h>
#include <cuda_bf16.h>
#include <cstdint>
#include <math.h>

#define BB 1024
#define DD 512
#define HH 1024
#define TT 8
#define EE 18

// ---------------------------------------------------------------------------
// Device scratch (no cudaMalloc allowed) — ~312 MB total
// ---------------------------------------------------------------------------
__device__ __nv_bfloat16 g_w1h[2][EE * DD * HH];  // W1 transposed [e][n(H)][k(D)] hi
__device__ __nv_bfloat16 g_w1l[2][EE * DD * HH];  // lo
__device__ __nv_bfloat16 g_w2h[2][EE * HH * DD];  // W2 transposed [e][n(D)][k(H)] hi
__device__ __nv_bfloat16 g_w2l[2][EE * HH * DD];
__device__ __nv_bfloat16 g_ah[BB * 9 * DD];       // activation planes (inputs / x1)
__device__ __nv_bfloat16 g_al[BB * 9 * DD];
__device__ __nv_bfloat16 g_hh[BB * EE * HH];      // hidden planes
__device__ __nv_bfloat16 g_hl[BB * EE * HH];
__device__ float g_eo  [BB * EE * DD];
__device__ float g_gate[BB * 9 * EE];
__device__ float g_x1  [BB * 9 * DD];

// ---------------------------------------------------------------------------
__device__ __forceinline__ uint32_t smem_u32(const void* p) {
    uint32_t a;
    asm("{ .reg .u64 t; cvta.to.shared.u64 t, %1; cvt.u32.u64 %0, t; }" : "=r"(a) : "l"(p));
    return a;
}
__device__ __forceinline__ void cp16(uint32_t dst, const void* src) {
    asm volatile("cp.async.cg.shared.global [%0], [%1], 16;" :: "r"(dst), "l"(src) : "memory");
}
#define CP_COMMIT() asm volatile("cp.async.commit_group;" ::: "memory")
#define CP_WAIT(n)  asm volatile("cp.async.wait_group %0;" :: "n"(n) : "memory")
#define LDSM4(r, addr) \
    asm volatile("ldmatrix.sync.aligned.m8n8.x4.shared.b16 {%0,%1,%2,%3}, [%4];" \
        : "=r"((r)[0]), "=r"((r)[1]), "=r"((r)[2]), "=r"((r)[3]) : "r"(addr))

__device__ __forceinline__ void mma16816(float* c, const uint32_t* a, const uint32_t* b) {
    asm volatile(
        "mma.sync.aligned.m16n8k16.row.col.f32.bf16.bf16.f32 "
        "{%0,%1,%2,%3}, {%4,%5,%6,%7}, {%8,%9}, {%0,%1,%2,%3};"
        : "+f"(c[0]), "+f"(c[1]), "+f"(c[2]), "+f"(c[3])
        : "r"(a[0]), "r"(a[1]), "r"(a[2]), "r"(a[3]), "r"(b[0]), "r"(b[1]));
}
__device__ __forceinline__ void split1(float x, __nv_bfloat16& h, __nv_bfloat16& l) {
    h = __float2bfloat16_rn(x);
    l = __float2bfloat16_rn(x - __bfloat162float(h));
}

// ===========================================================================
// Conversion kernels (run once per launch)
// ===========================================================================
__global__ __launch_bounds__(256) void conv_act(
    const float* __restrict__ src, __nv_bfloat16* __restrict__ hi,
    __nv_bfloat16* __restrict__ lo, int n4)
{
    int i = blockIdx.x * 256 + threadIdx.x;
    if (i >= n4) return;
    float4 v = ((const float4*)src)[i];
    __nv_bfloat16 h[4], l[4];
    split1(v.x, h[0], l[0]); split1(v.y, h[1], l[1]);
    split1(v.z, h[2], l[2]); split1(v.w, h[3], l[3]);
    ((uint2*)hi)[i] = *(uint2*)h;
    ((uint2*)lo)[i] = *(uint2*)l;
}

// Transpose-convert weights: W[e][k][n] fp32 -> Wt[e][n][k] bf16 hi/lo
__global__ __launch_bounds__(256) void conv_wt(
    const float* __restrict__ W, __nv_bfloat16* __restrict__ Whi,
    __nv_bfloat16* __restrict__ Wlo, int Kd, int Nd)
{
    __shared__ float t[32][33];
    const int e  = blockIdx.z;
    const int k0 = blockIdx.x * 32, n0 = blockIdx.y * 32;
    const int tx = threadIdx.x & 31, ty = threadIdx.x >> 5;  // 32 x 8
    const float* We = W + (size_t)e * Kd * Nd;
    #pragma unroll
    for (int i = 0; i < 4; i++)
        t[ty + 8 * i][tx] = We[(size_t)(k0 + ty + 8 * i) * Nd + n0 + tx];
    __syncthreads();
    #pragma unroll
    for (int i = 0; i < 4; i++) {
        const int n = n0 + ty + 8 * i;
        const float v = t[tx][ty + 8 * i];
        __nv_bfloat16 h, l;
        split1(v, h, l);
        const size_t off = ((size_t)e * Nd + n) * Kd + k0 + tx;
        Whi[off] = h; Wlo[off] = l;
    }
}

// ===========================================================================
// Tensor-core expert GEMM, bf16 hi/lo pre-split operands:
//   C[b,e,n] = act( sum_k A(b,e)[k] * Bt[e][n][k] + bias[e,n] )   (3 products)
// Tile 128x128, BK=32, cp.async double buffer, ldmatrix fragments.
// SMEM stage 40KB: [Ahi][Alo][Bhi][Blo], each 128 rows x 80B (64B data + pad).
// OUT1: relu + write bf16 hi/lo planes.  !OUT1: fp32 write.
// ===========================================================================
template<bool GATHER, bool OUT1, int NMAT, int K>
__global__ __launch_bounds__(256, 2) void tc_gemm(
    const __nv_bfloat16* __restrict__ Ahi, const __nv_bfloat16* __restrict__ Alo,
    int aStride,
    const __nv_bfloat16* __restrict__ Bhi, const __nv_bfloat16* __restrict__ Blo,
    const float* __restrict__ bias,
    float* __restrict__ Cf, __nv_bfloat16* __restrict__ Chi, __nv_bfloat16* __restrict__ Clo)
{
    constexpr int NS = K / 32;
    constexpr uint32_t PLANE = 10240;   // 128 * 80
    constexpr uint32_t STAGE = 40960;

    extern __shared__ char smraw[];
    const uint32_t smbase = smem_u32(smraw);

    const int e    = blockIdx.z;
    const int m0   = blockIdx.y * 128;
    const int n0   = blockIdx.x * 128;
    const int tid  = threadIdx.x;
    const int wid  = tid >> 5;
    const int lane = tid & 31;
    const int g    = lane >> 2;
    const int q    = lane & 3;
    const int mbase = (wid >> 2) * 64;
    const int nbase = (wid & 3) * 32;

    const __nv_bfloat16* Ahi_b = Ahi + (size_t)m0 * aStride + (size_t)(GATHER ? (e >> 1) : e) * K;
    const __nv_bfloat16* Alo_b = Alo + (size_t)m0 * aStride + (size_t)(GATHER ? (e >> 1) : e) * K;
    const __nv_bfloat16* Bhi_b = Bhi + ((size_t)e * NMAT + n0) * K;
    const __nv_bfloat16* Blo_b = Blo + ((size_t)e * NMAT + n0) * K;

    // per-thread ldmatrix base offsets (within a plane, excluding ks)
    const uint32_t aoff = (uint32_t)(mbase + (lane & 15)) * 80u + (uint32_t)(lane >> 4) * 16u;
    uint32_t boff[2];
    #pragma unroll
    for (int jj = 0; jj < 2; jj++)
        boff[jj] = (uint32_t)(nbase + jj * 16 + (lane & 7) + (((lane >> 4) & 1) << 3)) * 80u
                 + (uint32_t)((lane >> 3) & 1) * 16u;

    float acc[4][4][4];
    #pragma unroll
    for (int i = 0; i < 4; i++)
        #pragma unroll
        for (int j = 0; j < 4; j++)
            #pragma unroll
            for (int c = 0; c < 4; c++) acc[i][j][c] = 0.f;

    const int r0c = tid >> 2, c4 = tid & 3;

    auto loadStage = [&](int s, int buf) {
        const int k0 = s * 32;
        const uint32_t sb = smbase + (uint32_t)buf * STAGE;
        #pragma unroll
        for (int half = 0; half < 2; half++) {
            const int r = half * 64 + r0c;
            const uint32_t ro = (uint32_t)r * 80u + (uint32_t)c4 * 16u;
            cp16(sb + ro,             Ahi_b + (size_t)r * aStride + k0 + c4 * 8);
            cp16(sb + PLANE + ro,     Alo_b + (size_t)r * aStride + k0 + c4 * 8);
            cp16(sb + 2 * PLANE + ro, Bhi_b + (size_t)r * K + k0 + c4 * 8);
            cp16(sb + 3 * PLANE + ro, Blo_b + (size_t)r * K + k0 + c4 * 8);
        }
        CP_COMMIT();
    };

    auto compute = [&](int buf) {
        const uint32_t sb = smbase + (uint32_t)buf * STAGE;
        #pragma unroll
        for (int ks = 0; ks < 2; ks++) {
            const uint32_t ko = (uint32_t)ks * 32u;
            uint32_t af[4][4], bf[2][4], bl[2][4];
            LDSM4(bf[0], sb + 2 * PLANE + boff[0] + ko);
            LDSM4(bf[1], sb + 2 * PLANE + boff[1] + ko);
            #pragma unroll
            for (int i = 0; i < 4; i++)
                LDSM4(af[i], sb + aoff + (uint32_t)i * 1280u + ko);
            #pragma unroll
            for (int i = 0; i < 4; i++)
                #pragma unroll
                for (int j = 0; j < 4; j++)
                    mma16816(acc[i][j], af[i], &bf[j >> 1][(j & 1) * 2]);
            LDSM4(bl[0], sb + 3 * PLANE + boff[0] + ko);
            LDSM4(bl[1], sb + 3 * PLANE + boff[1] + ko);
            #pragma unroll
            for (int i = 0; i < 4; i++)
                #pragma unroll
                for (int j = 0; j < 4; j++)
                    mma16816(acc[i][j], af[i], &bl[j >> 1][(j & 1) * 2]);
            #pragma unroll
            for (int i = 0; i < 4; i++)
                LDSM4(af[i], sb + PLANE + aoff + (uint32_t)i * 1280u + ko);
            #pragma unroll
            for (int i = 0; i < 4; i++)
                #pragma unroll
                for (int j = 0; j < 4; j++)
                    mma16816(acc[i][j], af[i], &bf[j >> 1][(j & 1) * 2]);
        }
    };

    loadStage(0, 0);
    loadStage(1, 1);
    for (int s = 0; s < NS; s++) {
        if (s == NS - 1) { CP_WAIT(0); } else { CP_WAIT(1); }
        __syncthreads();
        compute(s & 1);
        __syncthreads();
        if (s + 2 < NS) loadStage(s + 2, s & 1);
    }

    // ---- epilogue ----
    #pragma unroll
    for (int i = 0; i < 4; i++) {
        const int rr0 = m0 + mbase + i * 16 + g;
        #pragma unroll
        for (int j = 0; j < 4; j++) {
            const int col = nbase + j * 8 + 2 * q;
            const float2 bb = *(const float2*)(bias + (size_t)e * NMAT + n0 + col);
            float v0 = acc[i][j][0] + bb.x;
            float v1 = acc[i][j][1] + bb.y;
            float v2 = acc[i][j][2] + bb.x;
            float v3 = acc[i][j][3] + bb.y;
            const size_t off0 = ((size_t)rr0 * EE + e) * NMAT + n0 + col;
            const size_t off1 = ((size_t)(rr0 + 8) * EE + e) * NMAT + n0 + col;
            if (OUT1) {
                v0 = fmaxf(v0, 0.f); v1 = fmaxf(v1, 0.f);
                v2 = fmaxf(v2, 0.f); v3 = fmaxf(v3, 0.f);
                __nv_bfloat16 h[4], l[4];
                split1(v0, h[0], l[0]); split1(v1, h[1], l[1]);
                split1(v2, h[2], l[2]); split1(v3, h[3], l[3]);
                *(uint32_t*)(Chi + off0) = *(uint32_t*)&h[0];
                *(uint32_t*)(Clo + off0) = *(uint32_t*)&l[0];
                *(uint32_t*)(Chi + off1) = *(uint32_t*)&h[2];
                *(uint32_t*)(Clo + off1) = *(uint32_t*)&l[2];
            } else {
                *(float2*)(Cf + off0) = make_float2(v0, v1);
                *(float2*)(Cf + off1) = make_float2(v2, v3);
            }
        }
    }
}

// ---------------------------------------------------------------------------
// Gating: g[b,m,:] = softmax( x[b,m,:] @ Wg[m] + bg[m] ) + add(m)
// ---------------------------------------------------------------------------
template<int M>
__global__ __launch_bounds__(256) void gate_kernel(
    const float* __restrict__ x, int xRows,
    const float* __restrict__ Wg, const float* __restrict__ bg,
    const float* __restrict__ sew_task, const float* __restrict__ sew_shared,
    int layer, float* __restrict__ g)
{
    __shared__ float sWg[DD * EE];
    __shared__ float sLog[32][EE];
    const int m  = blockIdx.y;
    const int b0 = blockIdx.x * 32;

    const float* Wgm = Wg + (size_t)m * DD * EE;
    for (int i = threadIdx.x; i < DD * EE; i += 256) sWg[i] = Wgm[i];
    __syncthreads();

    for (int p = threadIdx.x; p < 32 * EE; p += 256) {
        const int bl = p / EE, e = p % EE;
        const float* xr = x + ((size_t)(b0 + bl) * xRows + m) * DD;
        float s = bg[m * EE + e];
        for (int d = 0; d < DD; d += 4) {
            float4 xv = *(const float4*)(xr + d);
            s = fmaf(xv.x, sWg[(d + 0) * EE + e], s);
            s = fmaf(xv.y, sWg[(d + 1) * EE + e], s);
            s = fmaf(xv.z, sWg[(d + 2) * EE + e], s);
            s = fmaf(xv.w, sWg[(d + 3) * EE + e], s);
        }
        sLog[bl][e] = s;
    }
    __syncthreads();

    if (threadIdx.x < 32) {
        const int bl = threadIdx.x;
        float mx = -1e30f;
        #pragma unroll
        for (int e = 0; e < EE; e++) mx = fmaxf(mx, sLog[bl][e]);
        float ex[EE]; float sum = 0.f;
        #pragma unroll
        for (int e = 0; e < EE; e++) { ex[e] = expf(sLog[bl][e] - mx); sum += ex[e]; }
        const float inv = 1.f / sum;
        float* gp = g + ((size_t)(b0 + bl) * M + m) * EE;
        #pragma unroll
        for (int e = 0; e < EE; e++) gp[e] = ex[e] * inv;
        if (m < TT) {
            gp[2 * m + 0] += sew_task[(m * 2 + layer) * 2 + 0];
            gp[2 * m + 1] += sew_task[(m * 2 + layer) * 2 + 1];
        } else {
            gp[16] += sew_shared[0];
            gp[17] += sew_shared[1];
        }
    }
}

// ---------------------------------------------------------------------------
// Combine: out[b,m,d] = sum_e g[b,m,e] * eo[b,e,d]; optionally also write
// bf16 hi/lo planes of the result (feeds next layer's GEMM1).
// ---------------------------------------------------------------------------
template<int M, bool PLANES>
__global__ __launch_bounds__(512) void combine_kernel(
    const float* __restrict__ g, const float* __restrict__ eo,
    float* __restrict__ out, __nv_bfloat16* __restrict__ ohi,
    __nv_bfloat16* __restrict__ olo)
{
    __shared__ float sg[M * EE];
    const int b = blockIdx.x;
    for (int i = threadIdx.x; i < M * EE; i += 512) sg[i] = g[(size_t)b * M * EE + i];
    __syncthreads();

    const int d = threadIdx.x;
    float acc[M];
    #pragma unroll
    for (int mm = 0; mm < M; mm++) acc[mm] = 0.f;

    const float* eob = eo + (size_t)b * EE * DD + d;
    #pragma unroll
    for (int e = 0; e < EE; e++) {
        const float v = eob[(size_t)e * DD];
        #pragma unroll
        for (int mm = 0; mm < M; mm++) acc[mm] = fmaf(sg[mm * EE + e], v, acc[mm]);
    }
    #pragma unroll
    for (int mm = 0; mm < M; mm++) {
        const size_t off = ((size_t)b * M + mm) * DD + d;
        out[off] = acc[mm];
        if (PLANES) {
            __nv_bfloat16 h, l;
            split1(acc[mm], h, l);
            ohi[off] = h; olo[off] = l;
        }
    }
}

// ---------------------------------------------------------------------------
extern "C" void kernel_launch(void* const* d_in, const int* in_sizes, int n_in,
                              void* d_out, int out_size)
{
    const float* inputs   = (const float*)d_in[0];
    const float* W1_0     = (const float*)d_in[1];
    const float* b1_0     = (const float*)d_in[2];
    const float* W2_0     = (const float*)d_in[3];
    const float* b2_0     = (const float*)d_in[4];
    const float* Wg_0     = (const float*)d_in[5];
    const float* bg_0     = (const float*)d_in[6];
    const float* W1_1     = (const float*)d_in[7];
    const float* b1_1     = (const float*)d_in[8];
    const float* W2_1     = (const float*)d_in[9];
    const float* b2_1     = (const float*)d_in[10];
    const float* Wg_1     = (const float*)d_in[11];
    const float* bg_1     = (const float*)d_in[12];
    const float* sew_task = (const float*)d_in[13];
    const float* sew_shared = (const float*)d_in[14];

    __nv_bfloat16 *w1h0, *w1l0, *w1h1, *w1l1, *w2h0, *w2l0, *w2h1, *w2l1;
    __nv_bfloat16 *ah, *al, *hh, *hl;
    float *p_eo, *p_gate, *p_x1;
    cudaGetSymbolAddress((void**)&w1h0, g_w1h);
    cudaGetSymbolAddress((void**)&w1l0, g_w1l);
    cudaGetSymbolAddress((void**)&w2h0, g_w2h);
    cudaGetSymbolAddress((void**)&w2l0, g_w2l);
    w1h1 = w1h0 + (size_t)EE * DD * HH;  w1l1 = w1l0 + (size_t)EE * DD * HH;
    w2h1 = w2h0 + (size_t)EE * HH * DD;  w2l1 = w2l0 + (size_t)EE * HH * DD;
    cudaGetSymbolAddress((void**)&ah, g_ah);
    cudaGetSymbolAddress((void**)&al, g_al);
    cudaGetSymbolAddress((void**)&hh, g_hh);
    cudaGetSymbolAddress((void**)&hl, g_hl);
    cudaGetSymbolAddress((void**)&p_eo,   g_eo);
    cudaGetSymbolAddress((void**)&p_gate, g_gate);
    cudaGetSymbolAddress((void**)&p_x1,   g_x1);

    const int SMEM_DYN = 2 * 40960;   // 80 KB
    cudaFuncSetAttribute(tc_gemm<true,  true,  HH, DD>,
                         cudaFuncAttributeMaxDynamicSharedMemorySize, SMEM_DYN);
    cudaFuncSetAttribute(tc_gemm<false, false, DD, HH>,
                         cudaFuncAttributeMaxDynamicSharedMemorySize, SMEM_DYN);

    // ---- conversions (once per launch) ----
    conv_wt<<<dim3(DD/32, HH/32, EE), 256>>>(W1_0, w1h0, w1l0, DD, HH);
    conv_wt<<<dim3(DD/32, HH/32, EE), 256>>>(W1_1, w1h1, w1l1, DD, HH);
    conv_wt<<<dim3(HH/32, DD/32, EE), 256>>>(W2_0, w2h0, w2l0, HH, DD);
    conv_wt<<<dim3(HH/32, DD/32, EE), 256>>>(W2_1, w2h1, w2l1, HH, DD);
    {
        const int n4 = BB * 9 * DD / 4;
        conv_act<<<(n4 + 255) / 256, 256>>>(inputs, ah, al, n4);
    }

    const dim3 blk(256);

    // ---- Layer 0 ----
    tc_gemm<true,  true,  HH, DD><<<dim3(HH/128, BB/128, EE), blk, SMEM_DYN>>>(
        ah, al, 9 * DD, w1h0, w1l0, b1_0, nullptr, hh, hl);
    tc_gemm<false, false, DD, HH><<<dim3(DD/128, BB/128, EE), blk, SMEM_DYN>>>(
        hh, hl, EE * HH, w2h0, w2l0, b2_0, p_eo, nullptr, nullptr);
    gate_kernel<9><<<dim3(BB/32, 9), blk>>>(inputs, 9, Wg_0, bg_0, sew_task, sew_shared, 0, p_gate);
    combine_kernel<9, true><<<BB, 512>>>(p_gate, p_eo, p_x1, ah, al);

    // ---- Layer 1 ----
    tc_gemm<true,  true,  HH, DD><<<dim3(HH/128, BB/128, EE), blk, SMEM_DYN>>>(
        ah, al, 9 * DD, w1h1, w1l1, b1_1, nullptr, hh, hl);
    tc_gemm<false, false, DD, HH><<<dim3(DD/128, BB/128, EE), blk, SMEM_DYN>>>(
        hh, hl, EE * HH, w2h1, w2l1, b2_1, p_eo, nullptr, nullptr);
    gate_kernel<8><<<dim3(BB/32, 8), blk>>>(p_x1, 9, Wg_1, bg_1, sew_task, sew_shared, 1, p_gate);
    combine_kernel<8, false><<<BB, 512>>>(p_gate, p_eo, (float*)d_out, nullptr, nullptr);
}

// round 7
// speedup vs baseline: 2.3226x; 1.0326x over previous
#include <cuda_runtime.h>
#include <cuda_bf16.h>
#include <cstdint>
#include <math.h>

#define BB 1024
#define DD 512
#define HH 1024
#define TT 8
#define EE 18

// ---------------------------------------------------------------------------
// Device scratch (no cudaMalloc allowed)
// ---------------------------------------------------------------------------
__device__ __nv_bfloat16 g_w1h[2][EE * DD * HH];  // W1 transposed [e][n(H)][k(D)] hi
__device__ __nv_bfloat16 g_w1l[2][EE * DD * HH];  // lo
__device__ __nv_bfloat16 g_w2h[2][EE * HH * DD];  // W2 transposed [e][n(D)][k(H)] hi
__device__ __nv_bfloat16 g_w2l[2][EE * HH * DD];
__device__ __nv_bfloat16 g_ah[BB * 9 * DD];       // activation planes (inputs / x1)
__device__ __nv_bfloat16 g_al[BB * 9 * DD];
__device__ __nv_bfloat16 g_hh[BB * EE * HH];      // hidden planes
__device__ __nv_bfloat16 g_hl[BB * EE * HH];
__device__ float g_eo  [BB * EE * DD];
__device__ float g_gate[BB * 9 * EE];
__device__ float g_x1  [BB * 9 * DD];

// ---------------------------------------------------------------------------
__device__ __forceinline__ uint32_t smem_u32(const void* p) {
    uint32_t a;
    asm("{ .reg .u64 t; cvta.to.shared.u64 t, %1; cvt.u32.u64 %0, t; }" : "=r"(a) : "l"(p));
    return a;
}
__device__ __forceinline__ void cp16(uint32_t dst, const void* src) {
    asm volatile("cp.async.cg.shared.global [%0], [%1], 16;" :: "r"(dst), "l"(src) : "memory");
}
#define CP_COMMIT() asm volatile("cp.async.commit_group;" ::: "memory")
#define CP_WAIT(n)  asm volatile("cp.async.wait_group %0;" :: "n"(n) : "memory")
#define LDSM4(r, addr) \
    asm volatile("ldmatrix.sync.aligned.m8n8.x4.shared.b16 {%0,%1,%2,%3}, [%4];" \
        : "=r"((r)[0]), "=r"((r)[1]), "=r"((r)[2]), "=r"((r)[3]) : "r"(addr))

__device__ __forceinline__ void mma16816(float* c, const uint32_t* a, const uint32_t* b) {
    asm volatile(
        "mma.sync.aligned.m16n8k16.row.col.f32.bf16.bf16.f32 "
        "{%0,%1,%2,%3}, {%4,%5,%6,%7}, {%8,%9}, {%0,%1,%2,%3};"
        : "+f"(c[0]), "+f"(c[1]), "+f"(c[2]), "+f"(c[3])
        : "r"(a[0]), "r"(a[1]), "r"(a[2]), "r"(a[3]), "r"(b[0]), "r"(b[1]));
}
__device__ __forceinline__ void split1(float x, __nv_bfloat16& h, __nv_bfloat16& l) {
    h = __float2bfloat16_rn(x);
    l = __float2bfloat16_rn(x - __bfloat162float(h));
}

// ===========================================================================
// Conversion kernels (run once per launch)
// ===========================================================================
__global__ __launch_bounds__(256) void conv_act(
    const float* __restrict__ src, __nv_bfloat16* __restrict__ hi,
    __nv_bfloat16* __restrict__ lo, int n4)
{
    int i = blockIdx.x * 256 + threadIdx.x;
    if (i >= n4) return;
    float4 v = ((const float4*)src)[i];
    __nv_bfloat16 h[4], l[4];
    split1(v.x, h[0], l[0]); split1(v.y, h[1], l[1]);
    split1(v.z, h[2], l[2]); split1(v.w, h[3], l[3]);
    ((uint2*)hi)[i] = *(uint2*)h;
    ((uint2*)lo)[i] = *(uint2*)l;
}

// Transpose-convert weights: W[e][k][n] fp32 -> Wt[e][n][k] bf16 hi/lo
__global__ __launch_bounds__(256) void conv_wt(
    const float* __restrict__ W, __nv_bfloat16* __restrict__ Whi,
    __nv_bfloat16* __restrict__ Wlo, int Kd, int Nd)
{
    __shared__ float t[32][33];
    const int e  = blockIdx.z;
    const int k0 = blockIdx.x * 32, n0 = blockIdx.y * 32;
    const int tx = threadIdx.x & 31, ty = threadIdx.x >> 5;  // 32 x 8
    const float* We = W + (size_t)e * Kd * Nd;
    #pragma unroll
    for (int i = 0; i < 4; i++)
        t[ty + 8 * i][tx] = We[(size_t)(k0 + ty + 8 * i) * Nd + n0 + tx];
    __syncthreads();
    #pragma unroll
    for (int i = 0; i < 4; i++) {
        const int n = n0 + ty + 8 * i;
        const float v = t[tx][ty + 8 * i];
        __nv_bfloat16 h, l;
        split1(v, h, l);
        const size_t off = ((size_t)e * Nd + n) * Kd + k0 + tx;
        Whi[off] = h; Wlo[off] = l;
    }
}

// ===========================================================================
// Tensor-core expert GEMM, bf16 hi/lo pre-split operands, 3-product split:
//   C[b,e,n] = act( sum_k A(b,e)[k] * Bt[e][n][k] + bias[e,n] )
// Tile 128x128, BK=32, 3-stage cp.async pipeline (1 barrier per slab),
// XOR-swizzled 64B rows (no padding), ldmatrix fragments.
// SMEM stage 32KB: [Ahi][Alo][Bhi][Blo] planes of 128 x 64B.
// ===========================================================================
template<bool GATHER, bool OUT1, int NMAT, int K>
__global__ __launch_bounds__(256, 2) void tc_gemm(
    const __nv_bfloat16* __restrict__ Ahi, const __nv_bfloat16* __restrict__ Alo,
    int aStride,
    const __nv_bfloat16* __restrict__ Bhi, const __nv_bfloat16* __restrict__ Blo,
    const float* __restrict__ bias,
    float* __restrict__ Cf, __nv_bfloat16* __restrict__ Chi, __nv_bfloat16* __restrict__ Clo)
{
    constexpr int NS = K / 32;
    constexpr uint32_t PLANE = 8192;    // 128 rows * 64B
    constexpr uint32_t STAGE = 32768;   // 4 planes

    extern __shared__ char smraw[];
    const uint32_t smbase = smem_u32(smraw);

    const int e    = blockIdx.z;
    const int m0   = blockIdx.y * 128;
    const int n0   = blockIdx.x * 128;
    const int tid  = threadIdx.x;
    const int wid  = tid >> 5;
    const int lane = tid & 31;
    const int g    = lane >> 2;
    const int q    = lane & 3;
    const int mbase = (wid >> 2) * 64;
    const int nbase = (wid & 3) * 32;
    const int xr   = lane & 3;          // row&3 for all fragment rows

    const __nv_bfloat16* Ahi_b = Ahi + (size_t)m0 * aStride + (size_t)(GATHER ? (e >> 1) : e) * K;
    const __nv_bfloat16* Alo_b = Alo + (size_t)m0 * aStride + (size_t)(GATHER ? (e >> 1) : e) * K;
    const __nv_bfloat16* Bhi_b = Bhi + ((size_t)e * NMAT + n0) * K;
    const __nv_bfloat16* Blo_b = Blo + ((size_t)e * NMAT + n0) * K;

    // fragment row byte offsets (swizzle chunk added per ks)
    uint32_t arow[4], brow[2];
    #pragma unroll
    for (int i = 0; i < 4; i++)
        arow[i] = (uint32_t)(mbase + i * 16 + (lane & 15)) * 64u;
    #pragma unroll
    for (int jj = 0; jj < 2; jj++)
        brow[jj] = (uint32_t)(nbase + jj * 16 + (lane & 7) + (((lane >> 4) & 1) << 3)) * 64u;
    const int akc0 = lane >> 4;          // A k-chunk (pre-ks)
    const int bkc0 = (lane >> 3) & 1;    // B k-chunk (pre-ks)

    float acc[4][4][4];
    #pragma unroll
    for (int i = 0; i < 4; i++)
        #pragma unroll
        for (int j = 0; j < 4; j++)
            #pragma unroll
            for (int c = 0; c < 4; c++) acc[i][j][c] = 0.f;

    // cp.async mapping: thread handles rows (tid>>2) and (tid>>2)+64, chunk tid&3
    const int lr = tid >> 2, lc = tid & 3;

    auto loadStage = [&](int s, int buf) {
        const int k0 = s * 32;
        const uint32_t sb = smbase + (uint32_t)buf * STAGE;
        #pragma unroll
        for (int half = 0; half < 2; half++) {
            const int r = half * 64 + lr;
            const uint32_t ro = (uint32_t)r * 64u + (uint32_t)((lc ^ (r & 3)) << 4);
            const size_t ga = (size_t)r * aStride + k0 + lc * 8;
            const size_t gb = (size_t)r * K + k0 + lc * 8;
            cp16(sb + ro,             Ahi_b + ga);
            cp16(sb + PLANE + ro,     Alo_b + ga);
            cp16(sb + 2 * PLANE + ro, Bhi_b + gb);
            cp16(sb + 3 * PLANE + ro, Blo_b + gb);
        }
        CP_COMMIT();
    };

    auto compute = [&](int buf) {
        const uint32_t sb = smbase + (uint32_t)buf * STAGE;
        #pragma unroll
        for (int ks = 0; ks < 2; ks++) {
            const uint32_t ao = (uint32_t)(((akc0 + 2 * ks) ^ xr) << 4);
            const uint32_t bo = (uint32_t)(((bkc0 + 2 * ks) ^ xr) << 4);
            uint32_t af[4][4], bf[2][4], bl[2][4];
            LDSM4(bf[0], sb + 2 * PLANE + brow[0] + bo);
            LDSM4(bf[1], sb + 2 * PLANE + brow[1] + bo);
            #pragma unroll
            for (int i = 0; i < 4; i++)
                LDSM4(af[i], sb + arow[i] + ao);
            #pragma unroll
            for (int i = 0; i < 4; i++)
                #pragma unroll
                for (int j = 0; j < 4; j++)
                    mma16816(acc[i][j], af[i], &bf[j >> 1][(j & 1) * 2]);
            LDSM4(bl[0], sb + 3 * PLANE + brow[0] + bo);
            LDSM4(bl[1], sb + 3 * PLANE + brow[1] + bo);
            #pragma unroll
            for (int i = 0; i < 4; i++)
                #pragma unroll
                for (int j = 0; j < 4; j++)
                    mma16816(acc[i][j], af[i], &bl[j >> 1][(j & 1) * 2]);
            #pragma unroll
            for (int i = 0; i < 4; i++)
                LDSM4(af[i], sb + PLANE + arow[i] + ao);
            #pragma unroll
            for (int i = 0; i < 4; i++)
                #pragma unroll
                for (int j = 0; j < 4; j++)
                    mma16816(acc[i][j], af[i], &bf[j >> 1][(j & 1) * 2]);
        }
    };

    // ---- 3-stage pipeline, one barrier per slab ----
    loadStage(0, 0);
    loadStage(1, 1);
    int buf = 0;
    for (int s = 0; s < NS; s++) {
        if (s == NS - 1) { CP_WAIT(0); } else { CP_WAIT(1); }
        __syncthreads();
        if (s + 2 < NS) {
            int nb = buf + 2; if (nb >= 3) nb -= 3;
            loadStage(s + 2, nb);
        }
        compute(buf);
        if (++buf == 3) buf = 0;
    }

    // ---- epilogue ----
    #pragma unroll
    for (int i = 0; i < 4; i++) {
        const int rr0 = m0 + mbase + i * 16 + g;
        #pragma unroll
        for (int j = 0; j < 4; j++) {
            const int col = nbase + j * 8 + 2 * q;
            const float2 bb = *(const float2*)(bias + (size_t)e * NMAT + n0 + col);
            float v0 = acc[i][j][0] + bb.x;
            float v1 = acc[i][j][1] + bb.y;
            float v2 = acc[i][j][2] + bb.x;
            float v3 = acc[i][j][3] + bb.y;
            const size_t off0 = ((size_t)rr0 * EE + e) * NMAT + n0 + col;
            const size_t off1 = ((size_t)(rr0 + 8) * EE + e) * NMAT + n0 + col;
            if (OUT1) {
                v0 = fmaxf(v0, 0.f); v1 = fmaxf(v1, 0.f);
                v2 = fmaxf(v2, 0.f); v3 = fmaxf(v3, 0.f);
                __nv_bfloat16 h[4], l[4];
                split1(v0, h[0], l[0]); split1(v1, h[1], l[1]);
                split1(v2, h[2], l[2]); split1(v3, h[3], l[3]);
                *(uint32_t*)(Chi + off0) = *(uint32_t*)&h[0];
                *(uint32_t*)(Clo + off0) = *(uint32_t*)&l[0];
                *(uint32_t*)(Chi + off1) = *(uint32_t*)&h[2];
                *(uint32_t*)(Clo + off1) = *(uint32_t*)&l[2];
            } else {
                *(float2*)(Cf + off0) = make_float2(v0, v1);
                *(float2*)(Cf + off1) = make_float2(v2, v3);
            }
        }
    }
}

// ---------------------------------------------------------------------------
// Gating: g[b,m,:] = softmax( x[b,m,:] @ Wg[m] + bg[m] ) + add(m)
// ---------------------------------------------------------------------------
template<int M>
__global__ __launch_bounds__(256) void gate_kernel(
    const float* __restrict__ x, int xRows,
    const float* __restrict__ Wg, const float* __restrict__ bg,
    const float* __restrict__ sew_task, const float* __restrict__ sew_shared,
    int layer, float* __restrict__ g)
{
    __shared__ float sWg[DD * EE];
    __shared__ float sLog[32][EE];
    const int m  = blockIdx.y;
    const int b0 = blockIdx.x * 32;

    const float* Wgm = Wg + (size_t)m * DD * EE;
    for (int i = threadIdx.x; i < DD * EE; i += 256) sWg[i] = Wgm[i];
    __syncthreads();

    for (int p = threadIdx.x; p < 32 * EE; p += 256) {
        const int bl = p / EE, e = p % EE;
        const float* xr = x + ((size_t)(b0 + bl) * xRows + m) * DD;
        float s = bg[m * EE + e];
        for (int d = 0; d < DD; d += 4) {
            float4 xv = *(const float4*)(xr + d);
            s = fmaf(xv.x, sWg[(d + 0) * EE + e], s);
            s = fmaf(xv.y, sWg[(d + 1) * EE + e], s);
            s = fmaf(xv.z, sWg[(d + 2) * EE + e], s);
            s = fmaf(xv.w, sWg[(d + 3) * EE + e], s);
        }
        sLog[bl][e] = s;
    }
    __syncthreads();

    if (threadIdx.x < 32) {
        const int bl = threadIdx.x;
        float mx = -1e30f;
        #pragma unroll
        for (int e = 0; e < EE; e++) mx = fmaxf(mx, sLog[bl][e]);
        float ex[EE]; float sum = 0.f;
        #pragma unroll
        for (int e = 0; e < EE; e++) { ex[e] = expf(sLog[bl][e] - mx); sum += ex[e]; }
        const float inv = 1.f / sum;
        float* gp = g + ((size_t)(b0 + bl) * M + m) * EE;
        #pragma unroll
        for (int e = 0; e < EE; e++) gp[e] = ex[e] * inv;
        if (m < TT) {
            gp[2 * m + 0] += sew_task[(m * 2 + layer) * 2 + 0];
            gp[2 * m + 1] += sew_task[(m * 2 + layer) * 2 + 1];
        } else {
            gp[16] += sew_shared[0];
            gp[17] += sew_shared[1];
        }
    }
}

// ---------------------------------------------------------------------------
// Combine: out[b,m,d] = sum_e g[b,m,e] * eo[b,e,d]; optionally also write
// bf16 hi/lo planes of the result (feeds next layer's GEMM1).
// ---------------------------------------------------------------------------
template<int M, bool PLANES>
__global__ __launch_bounds__(512) void combine_kernel(
    const float* __restrict__ g, const float* __restrict__ eo,
    float* __restrict__ out, __nv_bfloat16* __restrict__ ohi,
    __nv_bfloat16* __restrict__ olo)
{
    __shared__ float sg[M * EE];
    const int b = blockIdx.x;
    for (int i = threadIdx.x; i < M * EE; i += 512) sg[i] = g[(size_t)b * M * EE + i];
    __syncthreads();

    const int d = threadIdx.x;
    float acc[M];
    #pragma unroll
    for (int mm = 0; mm < M; mm++) acc[mm] = 0.f;

    const float* eob = eo + (size_t)b * EE * DD + d;
    #pragma unroll
    for (int e = 0; e < EE; e++) {
        const float v = eob[(size_t)e * DD];
        #pragma unroll
        for (int mm = 0; mm < M; mm++) acc[mm] = fmaf(sg[mm * EE + e], v, acc[mm]);
    }
    #pragma unroll
    for (int mm = 0; mm < M; mm++) {
        const size_t off = ((size_t)b * M + mm) * DD + d;
        out[off] = acc[mm];
        if (PLANES) {
            __nv_bfloat16 h, l;
            split1(acc[mm], h, l);
            ohi[off] = h; olo[off] = l;
        }
    }
}

// ---------------------------------------------------------------------------
extern "C" void kernel_launch(void* const* d_in, const int* in_sizes, int n_in,
                              void* d_out, int out_size)
{
    const float* inputs   = (const float*)d_in[0];
    const float* W1_0     = (const float*)d_in[1];
    const float* b1_0     = (const float*)d_in[2];
    const float* W2_0     = (const float*)d_in[3];
    const float* b2_0     = (const float*)d_in[4];
    const float* Wg_0     = (const float*)d_in[5];
    const float* bg_0     = (const float*)d_in[6];
    const float* W1_1     = (const float*)d_in[7];
    const float* b1_1     = (const float*)d_in[8];
    const float* W2_1     = (const float*)d_in[9];
    const float* b2_1     = (const float*)d_in[10];
    const float* Wg_1     = (const float*)d_in[11];
    const float* bg_1     = (const float*)d_in[12];
    const float* sew_task = (const float*)d_in[13];
    const float* sew_shared = (const float*)d_in[14];

    __nv_bfloat16 *w1h0, *w1l0, *w1h1, *w1l1, *w2h0, *w2l0, *w2h1, *w2l1;
    __nv_bfloat16 *ah, *al, *hh, *hl;
    float *p_eo, *p_gate, *p_x1;
    cudaGetSymbolAddress((void**)&w1h0, g_w1h);
    cudaGetSymbolAddress((void**)&w1l0, g_w1l);
    cudaGetSymbolAddress((void**)&w2h0, g_w2h);
    cudaGetSymbolAddress((void**)&w2l0, g_w2l);
    w1h1 = w1h0 + (size_t)EE * DD * HH;  w1l1 = w1l0 + (size_t)EE * DD * HH;
    w2h1 = w2h0 + (size_t)EE * HH * DD;  w2l1 = w2l0 + (size_t)EE * HH * DD;
    cudaGetSymbolAddress((void**)&ah, g_ah);
    cudaGetSymbolAddress((void**)&al, g_al);
    cudaGetSymbolAddress((void**)&hh, g_hh);
    cudaGetSymbolAddress((void**)&hl, g_hl);
    cudaGetSymbolAddress((void**)&p_eo,   g_eo);
    cudaGetSymbolAddress((void**)&p_gate, g_gate);
    cudaGetSymbolAddress((void**)&p_x1,   g_x1);

    const int SMEM_DYN = 3 * 32768;   // 96 KB (3 stages)
    cudaFuncSetAttribute(tc_gemm<true,  true,  HH, DD>,
                         cudaFuncAttributeMaxDynamicSharedMemorySize, SMEM_DYN);
    cudaFuncSetAttribute(tc_gemm<false, false, DD, HH>,
                         cudaFuncAttributeMaxDynamicSharedMemorySize, SMEM_DYN);

    // ---- conversions (once per launch) ----
    conv_wt<<<dim3(DD/32, HH/32, EE), 256>>>(W1_0, w1h0, w1l0, DD, HH);
    conv_wt<<<dim3(DD/32, HH/32, EE), 256>>>(W1_1, w1h1, w1l1, DD, HH);
    conv_wt<<<dim3(HH/32, DD/32, EE), 256>>>(W2_0, w2h0, w2l0, HH, DD);
    conv_wt<<<dim3(HH/32, DD/32, EE), 256>>>(W2_1, w2h1, w2l1, HH, DD);
    {
        const int n4 = BB * 9 * DD / 4;
        conv_act<<<(n4 + 255) / 256, 256>>>(inputs, ah, al, n4);
    }

    const dim3 blk(256);

    // ---- Layer 0 ----
    tc_gemm<true,  true,  HH, DD><<<dim3(HH/128, BB/128, EE), blk, SMEM_DYN>>>(
        ah, al, 9 * DD, w1h0, w1l0, b1_0, nullptr, hh, hl);
    tc_gemm<false, false, DD, HH><<<dim3(DD/128, BB/128, EE), blk, SMEM_DYN>>>(
        hh, hl, EE * HH, w2h0, w2l0, b2_0, p_eo, nullptr, nullptr);
    gate_kernel<9><<<dim3(BB/32, 9), blk>>>(inputs, 9, Wg_0, bg_0, sew_task, sew_shared, 0, p_gate);
    combine_kernel<9, true><<<BB, 512>>>(p_gate, p_eo, p_x1, ah, al);

    // ---- Layer 1 ----
    tc_gemm<true,  true,  HH, DD><<<dim3(HH/128, BB/128, EE), blk, SMEM_DYN>>>(
        ah, al, 9 * DD, w1h1, w1l1, b1_1, nullptr, hh, hl);
    tc_gemm<false, false, DD, HH><<<dim3(DD/128, BB/128, EE), blk, SMEM_DYN>>>(
        hh, hl, EE * HH, w2h1, w2l1, b2_1, p_eo, nullptr, nullptr);
    gate_kernel<8><<<dim3(BB/32, 8), blk>>>(p_x1, 9, Wg_1, bg_1, sew_task, sew_shared, 1, p_gate);
    combine_kernel<8, false><<<BB, 512>>>(p_gate, p_eo, (float*)d_out, nullptr, nullptr);
}

// round 10
// speedup vs baseline: 2.8079x; 1.2089x over previous
#include <cuda_runtime.h>
#include <cuda_fp16.h>
#include <cstdint>
#include <math.h>

#define BB 1024
#define DD 512
#define HH 1024
#define TT 8
#define EE 18

// ---------------------------------------------------------------------------
// Device scratch (no cudaMalloc allowed)
// ---------------------------------------------------------------------------
__device__ __half g_w1[2][EE * DD * HH];   // W1 transposed [e][n(H)][k(D)] fp16
__device__ __half g_w2[2][EE * HH * DD];   // W2 transposed [e][n(D)][k(H)] fp16
__device__ __half g_ah[BB * 9 * DD];       // activation planes hi (inputs / x1)
__device__ __half g_al[BB * 9 * DD];       // activation planes lo
__device__ __half g_hh[BB * EE * HH];      // hidden planes hi
__device__ __half g_hl[BB * EE * HH];      // hidden planes lo
__device__ float g_eo  [BB * EE * DD];
__device__ float g_gate[BB * 9 * EE];
__device__ float g_x1  [BB * 9 * DD];

// ---------------------------------------------------------------------------
__device__ __forceinline__ uint32_t smem_u32(const void* p) {
    uint32_t a;
    asm("{ .reg .u64 t; cvta.to.shared.u64 t, %1; cvt.u32.u64 %0, t; }" : "=r"(a) : "l"(p));
    return a;
}
__device__ __forceinline__ void cp16(uint32_t dst, const void* src) {
    asm volatile("cp.async.cg.shared.global [%0], [%1], 16;" :: "r"(dst), "l"(src) : "memory");
}
#define CP_COMMIT() asm volatile("cp.async.commit_group;" ::: "memory")
#define CP_WAIT(n)  asm volatile("cp.async.wait_group %0;" :: "n"(n) : "memory")
#define LDSM4(r, addr) \
    asm volatile("ldmatrix.sync.aligned.m8n8.x4.shared.b16 {%0,%1,%2,%3}, [%4];" \
        : "=r"((r)[0]), "=r"((r)[1]), "=r"((r)[2]), "=r"((r)[3]) : "r"(addr))

__device__ __forceinline__ void mma16816(float* c, const uint32_t* a, const uint32_t* b) {
    asm volatile(
        "mma.sync.aligned.m16n8k16.row.col.f32.f16.f16.f32 "
        "{%0,%1,%2,%3}, {%4,%5,%6,%7}, {%8,%9}, {%0,%1,%2,%3};"
        : "+f"(c[0]), "+f"(c[1]), "+f"(c[2]), "+f"(c[3])
        : "r"(a[0]), "r"(a[1]), "r"(a[2]), "r"(a[3]), "r"(b[0]), "r"(b[1]));
}
__device__ __forceinline__ void split1h(float x, __half& h, __half& l) {
    h = __float2half_rn(x);
    l = __float2half_rn(x - __half2float(h));
}

// ===========================================================================
// Conversion kernels (run once per launch)
// ===========================================================================
__global__ __launch_bounds__(256) void conv_act(
    const float* __restrict__ src, __half* __restrict__ hi,
    __half* __restrict__ lo, int n4)
{
    int i = blockIdx.x * 256 + threadIdx.x;
    if (i >= n4) return;
    float4 v = ((const float4*)src)[i];
    __half h[4], l[4];
    split1h(v.x, h[0], l[0]); split1h(v.y, h[1], l[1]);
    split1h(v.z, h[2], l[2]); split1h(v.w, h[3], l[3]);
    ((uint2*)hi)[i] = *(uint2*)h;
    ((uint2*)lo)[i] = *(uint2*)l;
}

// Transpose-round weights: W[e][k][n] fp32 -> Wt[e][n][k] fp16
__global__ __launch_bounds__(256) void conv_wt(
    const float* __restrict__ W, __half* __restrict__ Wt, int Kd, int Nd)
{
    __shared__ float t[32][33];
    const int e  = blockIdx.z;
    const int k0 = blockIdx.x * 32, n0 = blockIdx.y * 32;
    const int tx = threadIdx.x & 31, ty = threadIdx.x >> 5;  // 32 x 8
    const float* We = W + (size_t)e * Kd * Nd;
    #pragma unroll
    for (int i = 0; i < 4; i++)
        t[ty + 8 * i][tx] = We[(size_t)(k0 + ty + 8 * i) * Nd + n0 + tx];
    __syncthreads();
    #pragma unroll
    for (int i = 0; i < 4; i++) {
        const int n = n0 + ty + 8 * i;
        Wt[((size_t)e * Nd + n) * Kd + k0 + tx] = __float2half_rn(t[tx][ty + 8 * i]);
    }
}

// ===========================================================================
// Tensor-core expert GEMM, fp16 2-product (A split hi/lo, B rounded):
//   C[b,e,n] = act( sum_k A(b,e)[k] * Bt[e][n][k] + bias[e,n] )
// Tile 128x128, BK=32, 3-stage cp.async pipeline, XOR-swizzled 64B rows.
// SMEM stage 24KB: [Ahi][Alo][Bh] planes of 128 x 64B (32 fp16).
// Both products share the same B fragments.
// ===========================================================================
template<bool GATHER, bool OUT1, int NMAT, int K>
__global__ __launch_bounds__(256, 2) void tc_gemm(
    const __half* __restrict__ Ahi, const __half* __restrict__ Alo,
    int aStride,
    const __half* __restrict__ Bt,
    const float* __restrict__ bias,
    float* __restrict__ Cf, __half* __restrict__ Chi, __half* __restrict__ Clo)
{
    constexpr int NS = K / 32;
    constexpr uint32_t PLANE = 8192;    // 128 rows * 64B
    constexpr uint32_t STAGE = 24576;   // 3 planes

    extern __shared__ char smraw[];
    const uint32_t smbase = smem_u32(smraw);

    const int e    = blockIdx.z;
    const int m0   = blockIdx.y * 128;
    const int n0   = blockIdx.x * 128;
    const int tid  = threadIdx.x;
    const int wid  = tid >> 5;
    const int lane = tid & 31;
    const int g    = lane >> 2;
    const int q    = lane & 3;
    const int mbase = (wid >> 2) * 64;
    const int nbase = (wid & 3) * 32;
    const int xr   = lane & 3;

    const __half* Ahi_b = Ahi + (size_t)m0 * aStride + (size_t)(GATHER ? (e >> 1) : e) * K;
    const __half* Alo_b = Alo + (size_t)m0 * aStride + (size_t)(GATHER ? (e >> 1) : e) * K;
    const __half* Bt_b  = Bt + ((size_t)e * NMAT + n0) * K;

    uint32_t arow[4], brow[2];
    #pragma unroll
    for (int i = 0; i < 4; i++)
        arow[i] = (uint32_t)(mbase + i * 16 + (lane & 15)) * 64u;
    #pragma unroll
    for (int jj = 0; jj < 2; jj++)
        brow[jj] = (uint32_t)(nbase + jj * 16 + (lane & 7) + (((lane >> 4) & 1) << 3)) * 64u;
    const int akc0 = lane >> 4;
    const int bkc0 = (lane >> 3) & 1;

    float acc[4][4][4];
    #pragma unroll
    for (int i = 0; i < 4; i++)
        #pragma unroll
        for (int j = 0; j < 4; j++)
            #pragma unroll
            for (int c = 0; c < 4; c++) acc[i][j][c] = 0.f;

    const int lr = tid >> 2, lc = tid & 3;

    auto loadStage = [&](int s, int buf) {
        const int k0 = s * 32;
        const uint32_t sb = smbase + (uint32_t)buf * STAGE;
        #pragma unroll
        for (int half = 0; half < 2; half++) {
            const int r = half * 64 + lr;
            const uint32_t ro = (uint32_t)r * 64u + (uint32_t)((lc ^ (r & 3)) << 4);
            const size_t ga = (size_t)r * aStride + k0 + lc * 8;
            cp16(sb + ro,             Ahi_b + ga);
            cp16(sb + PLANE + ro,     Alo_b + ga);
            cp16(sb + 2 * PLANE + ro, Bt_b + (size_t)r * K + k0 + lc * 8);
        }
        CP_COMMIT();
    };

    auto compute = [&](int buf) {
        const uint32_t sb = smbase + (uint32_t)buf * STAGE;
        #pragma unroll
        for (int ks = 0; ks < 2; ks++) {
            const uint32_t ao = (uint32_t)(((akc0 + 2 * ks) ^ xr) << 4);
            const uint32_t bo = (uint32_t)(((bkc0 + 2 * ks) ^ xr) << 4);
            uint32_t af[4][4], bf[2][4];
            LDSM4(bf[0], sb + 2 * PLANE + brow[0] + bo);
            LDSM4(bf[1], sb + 2 * PLANE + brow[1] + bo);
            #pragma unroll
            for (int i = 0; i < 4; i++)
                LDSM4(af[i], sb + arow[i] + ao);
            #pragma unroll
            for (int i = 0; i < 4; i++)
                #pragma unroll
                for (int j = 0; j < 4; j++)
                    mma16816(acc[i][j], af[i], &bf[j >> 1][(j & 1) * 2]);
            #pragma unroll
            for (int i = 0; i < 4; i++)
                LDSM4(af[i], sb + PLANE + arow[i] + ao);
            #pragma unroll
            for (int i = 0; i < 4; i++)
                #pragma unroll
                for (int j = 0; j < 4; j++)
                    mma16816(acc[i][j], af[i], &bf[j >> 1][(j & 1) * 2]);
        }
    };

    // ---- 3-stage pipeline, one barrier per slab ----
    loadStage(0, 0);
    loadStage(1, 1);
    int buf = 0;
    for (int s = 0; s < NS; s++) {
        if (s == NS - 1) { CP_WAIT(0); } else { CP_WAIT(1); }
        __syncthreads();
        if (s + 2 < NS) {
            int nb = buf + 2; if (nb >= 3) nb -= 3;
            loadStage(s + 2, nb);
        }
        compute(buf);
        if (++buf == 3) buf = 0;
    }

    // ---- epilogue ----
    #pragma unroll
    for (int i = 0; i < 4; i++) {
        const int rr0 = m0 + mbase + i * 16 + g;
        #pragma unroll
        for (int j = 0; j < 4; j++) {
            const int col = nbase + j * 8 + 2 * q;
            const float2 bb = *(const float2*)(bias + (size_t)e * NMAT + n0 + col);
            float v0 = acc[i][j][0] + bb.x;
            float v1 = acc[i][j][1] + bb.y;
            float v2 = acc[i][j][2] + bb.x;
            float v3 = acc[i][j][3] + bb.y;
            const size_t off0 = ((size_t)rr0 * EE + e) * NMAT + n0 + col;
            const size_t off1 = ((size_t)(rr0 + 8) * EE + e) * NMAT + n0 + col;
            if (OUT1) {
                v0 = fmaxf(v0, 0.f); v1 = fmaxf(v1, 0.f);
                v2 = fmaxf(v2, 0.f); v3 = fmaxf(v3, 0.f);
                __half h[4], l[4];
                split1h(v0, h[0], l[0]); split1h(v1, h[1], l[1]);
                split1h(v2, h[2], l[2]); split1h(v3, h[3], l[3]);
                *(uint32_t*)(Chi + off0) = *(uint32_t*)&h[0];
                *(uint32_t*)(Clo + off0) = *(uint32_t*)&l[0];
                *(uint32_t*)(Chi + off1) = *(uint32_t*)&h[2];
                *(uint32_t*)(Clo + off1) = *(uint32_t*)&l[2];
            } else {
                *(float2*)(Cf + off0) = make_float2(v0, v1);
                *(float2*)(Cf + off1) = make_float2(v2, v3);
            }
        }
    }
}

// ---------------------------------------------------------------------------
// Gating: g[b,m,:] = softmax( x[b,m,:] @ Wg[m] + bg[m] ) + add(m)
// ---------------------------------------------------------------------------
template<int M>
__global__ __launch_bounds__(256) void gate_kernel(
    const float* __restrict__ x, int xRows,
    const float* __restrict__ Wg, const float* __restrict__ bg,
    const float* __restrict__ sew_task, const float* __restrict__ sew_shared,
    int layer, float* __restrict__ g)
{
    __shared__ float sWg[DD * EE];
    __shared__ float sLog[32][EE];
    const int m  = blockIdx.y;
    const int b0 = blockIdx.x * 32;

    const float* Wgm = Wg + (size_t)m * DD * EE;
    for (int i = threadIdx.x; i < DD * EE; i += 256) sWg[i] = Wgm[i];
    __syncthreads();

    for (int p = threadIdx.x; p < 32 * EE; p += 256) {
        const int bl = p / EE, e = p % EE;
        const float* xr = x + ((size_t)(b0 + bl) * xRows + m) * DD;
        float s = bg[m * EE + e];
        for (int d = 0; d < DD; d += 4) {
            float4 xv = *(const float4*)(xr + d);
            s = fmaf(xv.x, sWg[(d + 0) * EE + e], s);
            s = fmaf(xv.y, sWg[(d + 1) * EE + e], s);
            s = fmaf(xv.z, sWg[(d + 2) * EE + e], s);
            s = fmaf(xv.w, sWg[(d + 3) * EE + e], s);
        }
        sLog[bl][e] = s;
    }
    __syncthreads();

    if (threadIdx.x < 32) {
        const int bl = threadIdx.x;
        float mx = -1e30f;
        #pragma unroll
        for (int e = 0; e < EE; e++) mx = fmaxf(mx, sLog[bl][e]);
        float ex[EE]; float sum = 0.f;
        #pragma unroll
        for (int e = 0; e < EE; e++) { ex[e] = expf(sLog[bl][e] - mx); sum += ex[e]; }
        const float inv = 1.f / sum;
        float* gp = g + ((size_t)(b0 + bl) * M + m) * EE;
        #pragma unroll
        for (int e = 0; e < EE; e++) gp[e] = ex[e] * inv;
        if (m < TT) {
            gp[2 * m + 0] += sew_task[(m * 2 + layer) * 2 + 0];
            gp[2 * m + 1] += sew_task[(m * 2 + layer) * 2 + 1];
        } else {
            gp[16] += sew_shared[0];
            gp[17] += sew_shared[1];
        }
    }
}

// ---------------------------------------------------------------------------
// Combine: out[b,m,d] = sum_e g[b,m,e] * eo[b,e,d]; optionally also write
// fp16 hi/lo planes of the result (feeds next layer's GEMM1).
// ---------------------------------------------------------------------------
template<int M, bool PLANES>
__global__ __launch_bounds__(512) void combine_kernel(
    const float* __restrict__ g, const float* __restrict__ eo,
    float* __restrict__ out, __half* __restrict__ ohi,
    __half* __restrict__ olo)
{
    __shared__ float sg[M * EE];
    const int b = blockIdx.x;
    for (int i = threadIdx.x; i < M * EE; i += 512) sg[i] = g[(size_t)b * M * EE + i];
    __syncthreads();

    const int d = threadIdx.x;
    float acc[M];
    #pragma unroll
    for (int mm = 0; mm < M; mm++) acc[mm] = 0.f;

    const float* eob = eo + (size_t)b * EE * DD + d;
    #pragma unroll
    for (int e = 0; e < EE; e++) {
        const float v = eob[(size_t)e * DD];
        #pragma unroll
        for (int mm = 0; mm < M; mm++) acc[mm] = fmaf(sg[mm * EE + e], v, acc[mm]);
    }
    #pragma unroll
    for (int mm = 0; mm < M; mm++) {
        const size_t off = ((size_t)b * M + mm) * DD + d;
        out[off] = acc[mm];
        if (PLANES) {
            __half h, l;
            split1h(acc[mm], h, l);
            ohi[off] = h; olo[off] = l;
        }
    }
}

// ---------------------------------------------------------------------------
extern "C" void kernel_launch(void* const* d_in, const int* in_sizes, int n_in,
                              void* d_out, int out_size)
{
    const float* inputs   = (const float*)d_in[0];
    const float* W1_0     = (const float*)d_in[1];
    const float* b1_0     = (const float*)d_in[2];
    const float* W2_0     = (const float*)d_in[3];
    const float* b2_0     = (const float*)d_in[4];
    const float* Wg_0     = (const float*)d_in[5];
    const float* bg_0     = (const float*)d_in[6];
    const float* W1_1     = (const float*)d_in[7];
    const float* b1_1     = (const float*)d_in[8];
    const float* W2_1     = (const float*)d_in[9];
    const float* b2_1     = (const float*)d_in[10];
    const float* Wg_1     = (const float*)d_in[11];
    const float* bg_1     = (const float*)d_in[12];
    const float* sew_task = (const float*)d_in[13];
    const float* sew_shared = (const float*)d_in[14];

    __half *w1_0p, *w1_1p, *w2_0p, *w2_1p, *ah, *al, *hh, *hl;
    float *p_eo, *p_gate, *p_x1;
    cudaGetSymbolAddress((void**)&w1_0p, g_w1);
    cudaGetSymbolAddress((void**)&w2_0p, g_w2);
    w1_1p = w1_0p + (size_t)EE * DD * HH;
    w2_1p = w2_0p + (size_t)EE * HH * DD;
    cudaGetSymbolAddress((void**)&ah, g_ah);
    cudaGetSymbolAddress((void**)&al, g_al);
    cudaGetSymbolAddress((void**)&hh, g_hh);
    cudaGetSymbolAddress((void**)&hl, g_hl);
    cudaGetSymbolAddress((void**)&p_eo,   g_eo);
    cudaGetSymbolAddress((void**)&p_gate, g_gate);
    cudaGetSymbolAddress((void**)&p_x1,   g_x1);

    const int SMEM_DYN = 3 * 24576;   // 72 KB (3 stages x 3 planes)
    cudaFuncSetAttribute(tc_gemm<true,  true,  HH, DD>,
                         cudaFuncAttributeMaxDynamicSharedMemorySize, SMEM_DYN);
    cudaFuncSetAttribute(tc_gemm<false, false, DD, HH>,
                         cudaFuncAttributeMaxDynamicSharedMemorySize, SMEM_DYN);

    // ---- conversions (once per launch) ----
    conv_wt<<<dim3(DD/32, HH/32, EE), 256>>>(W1_0, w1_0p, DD, HH);
    conv_wt<<<dim3(DD/32, HH/32, EE), 256>>>(W1_1, w1_1p, DD, HH);
    conv_wt<<<dim3(HH/32, DD/32, EE), 256>>>(W2_0, w2_0p, HH, DD);
    conv_wt<<<dim3(HH/32, DD/32, EE), 256>>>(W2_1, w2_1p, HH, DD);
    {
        const int n4 = BB * 9 * DD / 4;
        conv_act<<<(n4 + 255) / 256, 256>>>(inputs, ah, al, n4);
    }

    const dim3 blk(256);

    // ---- Layer 0 ----
    tc_gemm<true,  true,  HH, DD><<<dim3(HH/128, BB/128, EE), blk, SMEM_DYN>>>(
        ah, al, 9 * DD, w1_0p, b1_0, nullptr, hh, hl);
    tc_gemm<false, false, DD, HH><<<dim3(DD/128, BB/128, EE), blk, SMEM_DYN>>>(
        hh, hl, EE * HH, w2_0p, b2_0, p_eo, nullptr, nullptr);
    gate_kernel<9><<<dim3(BB/32, 9), blk>>>(inputs, 9, Wg_0, bg_0, sew_task, sew_shared, 0, p_gate);
    combine_kernel<9, true><<<BB, 512>>>(p_gate, p_eo, p_x1, ah, al);

    // ---- Layer 1 ----
    tc_gemm<true,  true,  HH, DD><<<dim3(HH/128, BB/128, EE), blk, SMEM_DYN>>>(
        ah, al, 9 * DD, w1_1p, b1_1, nullptr, hh, hl);
    tc_gemm<false, false, DD, HH><<<dim3(DD/128, BB/128, EE), blk, SMEM_DYN>>>(
        hh, hl, EE * HH, w2_1p, b2_1, p_eo, nullptr, nullptr);
    gate_kernel<8><<<dim3(BB/32, 8), blk>>>(p_x1, 9, Wg_1, bg_1, sew_task, sew_shared, 1, p_gate);
    combine_kernel<8, false><<<BB, 512>>>(p_gate, p_eo, (float*)d_out, nullptr, nullptr);
}